// round 8
// baseline (speedup 1.0000x reference)
#include <cuda_runtime.h>
#include <cstdint>

#define FEAT_DIM  8
#define TABLE     1048577
#define LAST_ROW  (TABLE - 1)

// Fused 3-level kernel. 2 lanes per point; each lane owns 16B (4 dims) of
// every gathered 32B row via one LDG.128 per corner. Gather wavefront count
// (1 per random row) is structural; fusion removes the out-RMW and repeated
// coord/launch overhead of the 3-pass version.
__global__ __launch_bounds__(256) void octree_fused_kernel(
    const float* __restrict__ coord,     // (N,3)
    const float* __restrict__ features,  // (3,TABLE,8)
    const int*   __restrict__ indices,   // (3,N,8)
    float*       __restrict__ out,       // (N,8)
    int n)
{
    const int lane  = threadIdx.x & 31;
    const int gwarp = (blockIdx.x * blockDim.x + threadIdx.x) >> 5;
    const int half  = lane & 1;                 // which 16B half of the row
    const int p0    = gwarp * 16 + (lane >> 1);
    const bool valid = (p0 < n);
    const int p = valid ? p0 : (n > 0 ? n - 1 : 0);

    const float x = __ldcs(&coord[3 * (size_t)p + 0]);
    const float y = __ldcs(&coord[3 * (size_t)p + 1]);
    const float z = __ldcs(&coord[3 * (size_t)p + 2]);

    float a0 = 0.f, a1 = 0.f, a2 = 0.f, a3 = 0.f;

    #pragma unroll
    for (int i = 0; i < 3; i++) {
        // pass i: indices[i] pairs with features[2-i], level = 12-i
        const float s = (float)(1 << (11 - i));   // 2^(level-1)
        const float* feat = features + (size_t)(2 - i) * TABLE * FEAT_DIM;
        const int*   idx  = indices + (size_t)i * n * 8;

        float cx = fmaf(s, x, s), cy = fmaf(s, y, s), cz = fmaf(s, z, s);
        float dx = cx - floorf(cx), dy = cy - floorf(cy), dz = cz - floorf(cz);
        dx = dx * dx * fmaf(-2.f, dx, 3.f);   // smoothstep 3d^2-2d^3
        dy = dy * dy * fmaf(-2.f, dy, 3.f);
        dz = dz * dz * fmaf(-2.f, dz, 3.f);

        const float ex = 1.f - dx, ey = 1.f - dy, ez = 1.f - dz;
        const float exey = ex * ey, exdy = ex * dy;
        const float dxey = dx * ey, dxdy = dx * dy;
        float w[8];
        w[0] = exey * ez; w[1] = exey * dz;
        w[2] = exdy * ez; w[3] = exdy * dz;
        w[4] = dxey * ez; w[5] = dxey * dz;
        w[6] = dxdy * ez; w[7] = dxdy * dz;

        // this point's 8 indices (lane pairs read same 32B: L1 broadcast)
        const int4* ip = reinterpret_cast<const int4*>(idx + (size_t)p * 8);
        const int4 ia = __ldcs(ip);
        const int4 ib = __ldcs(ip + 1);
        const int id[8] = {ia.x, ia.y, ia.z, ia.w, ib.x, ib.y, ib.z, ib.w};

        const char* fb = (const char*)feat + half * 16;   // my 16B half

        #pragma unroll
        for (int c = 0; c < 8; c++) {
            float wc = (id[c] == LAST_ROW) ? 0.f : w[c];  // features[:,-1,:]=0
            const float4 g = __ldg(reinterpret_cast<const float4*>(
                fb + (size_t)(unsigned)id[c] * 32u));
            a0 = fmaf(wc, g.x, a0);
            a1 = fmaf(wc, g.y, a1);
            a2 = fmaf(wc, g.z, a2);
            a3 = fmaf(wc, g.w, a3);
        }
    }

    if (valid) {
        float4* op = reinterpret_cast<float4*>(out + (size_t)p * 8 + half * 4);
        *op = make_float4(a0, a1, a2, a3);
    }
}

extern "C" void kernel_launch(void* const* d_in, const int* in_sizes, int n_in,
                              void* d_out, int out_size)
{
    const float* coord    = (const float*)d_in[0];  // (N,3)
    const float* features = (const float*)d_in[1];  // (3,TABLE,8)
    const int*   indices  = (const int*)d_in[2];    // (3,N,8)
    float*       out      = (float*)d_out;          // (N,8)

    const int n = in_sizes[0] / 3;
    const int threads = 256;
    const int blocks = (n + 127) / 128;  // 128 points/block (8 warps x 16)

    octree_fused_kernel<<<blocks, threads>>>(coord, features, indices, out, n);
}

// round 9
// speedup vs baseline: 1.3650x; 1.3650x over previous
#include <cuda_runtime.h>
#include <cstdint>

#define FEAT_DIM  8
#define TABLE     1048577
#define LAST_ROW  (TABLE - 1)

// 3 passes (one table per pass -> L2-resident gathers; proven in R7).
// 2 lanes per point, LDG.128 half-row gathers; NOW 2 points per thread so
// each thread has 16 independent gathers in flight (hide L2 latency, push
// the L1 wavefront pipe from ~76% toward saturation).
template <bool FIRST>
__global__ __launch_bounds__(256) void octree_level_kernel(
    const float* __restrict__ coord,   // (N,3)
    const float* __restrict__ feat,    // (TABLE,8) for this level
    const int*   __restrict__ idx,     // (N,8) for this level
    float*       __restrict__ out,     // (N,8)
    int n, float s)                    // s = 2^(level-1)
{
    const int lane  = threadIdx.x & 31;
    const int gwarp = (blockIdx.x * blockDim.x + threadIdx.x) >> 5;
    const int half  = lane & 1;                  // which 16B half of the row
    const int base  = gwarp * 32 + (lane >> 1);  // warp covers 32 points
    const int nclamp = (n > 0 ? n - 1 : 0);

    const int pA0 = base;           const bool vA = (pA0 < n);
    const int pB0 = base + 16;      const bool vB = (pB0 < n);
    const int pA = vA ? pA0 : nclamp;
    const int pB = vB ? pB0 : nclamp;

    float wA[8], wB[8];
    #pragma unroll
    for (int q = 0; q < 2; q++) {
        const int p = q ? pB : pA;
        float* w = q ? wB : wA;
        const float x = __ldcs(&coord[3 * (size_t)p + 0]);
        const float y = __ldcs(&coord[3 * (size_t)p + 1]);
        const float z = __ldcs(&coord[3 * (size_t)p + 2]);
        float cx = fmaf(s, x, s), cy = fmaf(s, y, s), cz = fmaf(s, z, s);
        float dx = cx - floorf(cx), dy = cy - floorf(cy), dz = cz - floorf(cz);
        dx = dx * dx * fmaf(-2.f, dx, 3.f);   // smoothstep 3d^2-2d^3
        dy = dy * dy * fmaf(-2.f, dy, 3.f);
        dz = dz * dz * fmaf(-2.f, dz, 3.f);
        const float ex = 1.f - dx, ey = 1.f - dy, ez = 1.f - dz;
        const float exey = ex * ey, exdy = ex * dy;
        const float dxey = dx * ey, dxdy = dx * dy;
        w[0] = exey * ez; w[1] = exey * dz;
        w[2] = exdy * ez; w[3] = exdy * dz;
        w[4] = dxey * ez; w[5] = dxey * dz;
        w[6] = dxdy * ez; w[7] = dxdy * dz;
    }

    // indices: lane pairs read the same 32B (L1 broadcast); warp-wide the
    // 4 loads cover a contiguous 1KB window.
    const int4* ipA = reinterpret_cast<const int4*>(idx + (size_t)pA * 8);
    const int4* ipB = reinterpret_cast<const int4*>(idx + (size_t)pB * 8);
    const int4 iA0 = __ldcs(ipA), iA1 = __ldcs(ipA + 1);
    const int4 iB0 = __ldcs(ipB), iB1 = __ldcs(ipB + 1);
    const int idA[8] = {iA0.x, iA0.y, iA0.z, iA0.w, iA1.x, iA1.y, iA1.z, iA1.w};
    const int idB[8] = {iB0.x, iB0.y, iB0.z, iB0.w, iB1.x, iB1.y, iB1.z, iB1.w};

    const char* fb = (const char*)feat + half * 16;   // my 16B half

    float aA0, aA1, aA2, aA3, aB0, aB1, aB2, aB3;
    if (FIRST) {
        aA0 = aA1 = aA2 = aA3 = 0.f;
        aB0 = aB1 = aB2 = aB3 = 0.f;
    } else {
        const float4 pvA = __ldcs(reinterpret_cast<const float4*>(
            out + (size_t)pA * 8 + half * 4));
        const float4 pvB = __ldcs(reinterpret_cast<const float4*>(
            out + (size_t)pB * 8 + half * 4));
        aA0 = pvA.x; aA1 = pvA.y; aA2 = pvA.z; aA3 = pvA.w;
        aB0 = pvB.x; aB1 = pvB.y; aB2 = pvB.z; aB3 = pvB.w;
    }

    #pragma unroll
    for (int c = 0; c < 8; c++) {
        const float wcA = (idA[c] == LAST_ROW) ? 0.f : wA[c]; // features[:,-1,:]=0
        const float wcB = (idB[c] == LAST_ROW) ? 0.f : wB[c];
        const float4 gA = __ldg(reinterpret_cast<const float4*>(
            fb + (size_t)(unsigned)idA[c] * 32u));
        const float4 gB = __ldg(reinterpret_cast<const float4*>(
            fb + (size_t)(unsigned)idB[c] * 32u));
        aA0 = fmaf(wcA, gA.x, aA0);
        aA1 = fmaf(wcA, gA.y, aA1);
        aA2 = fmaf(wcA, gA.z, aA2);
        aA3 = fmaf(wcA, gA.w, aA3);
        aB0 = fmaf(wcB, gB.x, aB0);
        aB1 = fmaf(wcB, gB.y, aB1);
        aB2 = fmaf(wcB, gB.z, aB2);
        aB3 = fmaf(wcB, gB.w, aB3);
    }

    if (vA) {
        float4* op = reinterpret_cast<float4*>(out + (size_t)pA * 8 + half * 4);
        *op = make_float4(aA0, aA1, aA2, aA3);
    }
    if (vB) {
        float4* op = reinterpret_cast<float4*>(out + (size_t)pB * 8 + half * 4);
        *op = make_float4(aB0, aB1, aB2, aB3);
    }
}

extern "C" void kernel_launch(void* const* d_in, const int* in_sizes, int n_in,
                              void* d_out, int out_size)
{
    const float* coord    = (const float*)d_in[0];  // (N,3)
    const float* features = (const float*)d_in[1];  // (3,TABLE,8)
    const int*   indices  = (const int*)d_in[2];    // (3,N,8)
    float*       out      = (float*)d_out;          // (N,8)

    const int n = in_sizes[0] / 3;
    const int threads = 256;
    const int blocks = (n + 255) / 256;  // 256 points/block (8 warps x 32)

    // pass i: indices[i] pairs with features[2-i], level = 12-i, s = 2^(level-1)
    octree_level_kernel<true><<<blocks, threads>>>(
        coord, features + (size_t)2 * TABLE * FEAT_DIM,
        indices + (size_t)0 * n * 8, out, n, 2048.f);
    octree_level_kernel<false><<<blocks, threads>>>(
        coord, features + (size_t)1 * TABLE * FEAT_DIM,
        indices + (size_t)1 * n * 8, out, n, 1024.f);
    octree_level_kernel<false><<<blocks, threads>>>(
        coord, features + (size_t)0 * TABLE * FEAT_DIM,
        indices + (size_t)2 * n * 8, out, n, 512.f);
}

// round 12
// speedup vs baseline: 1.3789x; 1.0102x over previous
#include <cuda_runtime.h>
#include <cstdint>

#define FEAT_DIM  8
#define TABLE     1048577
#define LAST_ROW  (TABLE - 1)

// 3 passes (one 33.5MB table per pass -> L2-resident gathers; proven R7/R9).
// 2 lanes per point, one LDG.128 half-row per corner. Gathers use __ldcg
// (L2-only): the table never hits in 228KB L1, so skipping L1 allocation
// removes fill/replay overhead from the l1tex pipe.
template <bool FIRST>
__global__ __launch_bounds__(256) void octree_level_kernel(
    const float* __restrict__ coord,   // (N,3)
    const float* __restrict__ feat,    // (TABLE,8) for this level
    const int*   __restrict__ idx,     // (N,8) for this level
    float*       __restrict__ out,     // (N,8)
    int n, float s)                    // s = 2^(level-1)
{
    const int lane  = threadIdx.x & 31;
    const int gwarp = (blockIdx.x * blockDim.x + threadIdx.x) >> 5;
    const int half  = lane & 1;                 // which 16B half of the row
    const int p0    = gwarp * 16 + (lane >> 1);
    const bool valid = (p0 < n);
    const int p = valid ? p0 : (n > 0 ? n - 1 : 0);

    const float x = __ldcs(&coord[3 * (size_t)p + 0]);
    const float y = __ldcs(&coord[3 * (size_t)p + 1]);
    const float z = __ldcs(&coord[3 * (size_t)p + 2]);
    float cx = fmaf(s, x, s), cy = fmaf(s, y, s), cz = fmaf(s, z, s);
    float dx = cx - floorf(cx), dy = cy - floorf(cy), dz = cz - floorf(cz);
    dx = dx * dx * fmaf(-2.f, dx, 3.f);   // smoothstep 3d^2-2d^3
    dy = dy * dy * fmaf(-2.f, dy, 3.f);
    dz = dz * dz * fmaf(-2.f, dz, 3.f);

    const float ex = 1.f - dx, ey = 1.f - dy, ez = 1.f - dz;
    const float exey = ex * ey, exdy = ex * dy;
    const float dxey = dx * ey, dxdy = dx * dy;
    float w[8];
    w[0] = exey * ez; w[1] = exey * dz;
    w[2] = exdy * ez; w[3] = exdy * dz;
    w[4] = dxey * ez; w[5] = dxey * dz;
    w[6] = dxdy * ez; w[7] = dxdy * dz;

    // this point's 8 indices (lane pairs read the same 32B: L1 broadcast)
    const int4* ip = reinterpret_cast<const int4*>(idx + (size_t)p * 8);
    const int4 ia = __ldcs(ip);
    const int4 ib = __ldcs(ip + 1);
    const int id[8] = {ia.x, ia.y, ia.z, ia.w, ib.x, ib.y, ib.z, ib.w};

    const char* fb = (const char*)feat + half * 16;   // my 16B half
    float a0, a1, a2, a3;
    if (FIRST) { a0 = a1 = a2 = a3 = 0.f; }
    else {
        const float4 prev = __ldcs(reinterpret_cast<const float4*>(
            out + (size_t)p * 8 + half * 4));
        a0 = prev.x; a1 = prev.y; a2 = prev.z; a3 = prev.w;
    }

    #pragma unroll
    for (int c = 0; c < 8; c++) {
        float wc = (id[c] == LAST_ROW) ? 0.f : w[c];  // features[:,-1,:]=0
        const float4 g = __ldcg(reinterpret_cast<const float4*>(
            fb + (size_t)(unsigned)id[c] * 32u));     // L2-only gather
        a0 = fmaf(wc, g.x, a0);
        a1 = fmaf(wc, g.y, a1);
        a2 = fmaf(wc, g.z, a2);
        a3 = fmaf(wc, g.w, a3);
    }

    if (valid) {
        float4* op = reinterpret_cast<float4*>(out + (size_t)p * 8 + half * 4);
        *op = make_float4(a0, a1, a2, a3);
    }
}

extern "C" void kernel_launch(void* const* d_in, const int* in_sizes, int n_in,
                              void* d_out, int out_size)
{
    const float* coord    = (const float*)d_in[0];  // (N,3)
    const float* features = (const float*)d_in[1];  // (3,TABLE,8)
    const int*   indices  = (const int*)d_in[2];    // (3,N,8)
    float*       out      = (float*)d_out;          // (N,8)

    const int n = in_sizes[0] / 3;
    const int threads = 256;
    const int blocks = (n + 127) / 128;  // 128 points/block (8 warps x 16)

    // pass i: indices[i] pairs with features[2-i], level = 12-i, s = 2^(level-1)
    octree_level_kernel<true><<<blocks, threads>>>(
        coord, features + (size_t)2 * TABLE * FEAT_DIM,
        indices + (size_t)0 * n * 8, out, n, 2048.f);
    octree_level_kernel<false><<<blocks, threads>>>(
        coord, features + (size_t)1 * TABLE * FEAT_DIM,
        indices + (size_t)1 * n * 8, out, n, 1024.f);
    octree_level_kernel<false><<<blocks, threads>>>(
        coord, features + (size_t)0 * TABLE * FEAT_DIM,
        indices + (size_t)2 * n * 8, out, n, 512.f);
}